// round 6
// baseline (speedup 1.0000x reference)
#include <cuda_runtime.h>

// Problem constants
#define DD    128   // feature dim
#define CO    16    // output channels
#define PPV   16    // P*P
#define HG    32    // sqrt(N)
#define NB    32    // batch
#define NT    64    // n-rows per block
#define WPAD  132   // W smem row stride (floats)
#define XWPAD 20    // xw smem row stride (floats): phase-2 LDS.128 conflict-free

// packed fp32x2 FMA (sm_103a; ptxas never auto-generates -> inline PTX)
__device__ __forceinline__ void ffma2(unsigned long long& d,
                                      unsigned long long a,
                                      unsigned long long b) {
    asm("fma.rn.f32x2 %0, %1, %2, %0;" : "+l"(d) : "l"(a), "l"(b));
}
__device__ __forceinline__ float hsum2(unsigned long long v) {
    float lo = __uint_as_float((unsigned)(v & 0xffffffffull));
    float hi = __uint_as_float((unsigned)(v >> 32));
    return lo + hi;
}

// ---------------------------------------------------------------------------
// One block per (n-tile=64 rows, b). 256 threads, grid (16,32)=512, 1 wave.
//  Phase 0 : W -> smem (8.4 KB), mask row.
//  Phase 1 : GEMV 1 row x 4 p per thread via fp32x2 FMA; x straight from gmem.
//  Phase 1b: cb[c][p] = emb[c].W[p]+bias[p] (256 dots, 1/thread, emb from L2).
//  Phase 2 : each thread owns (image row, col-float4); 16 channel stores,
//            each a warp-wide 512B fully-coalesced STG.128.
// ---------------------------------------------------------------------------
__global__ void __launch_bounds__(256, 4)
decoder_fused(const float* __restrict__ x,
              const float* __restrict__ W,
              const float* __restrict__ emb,
              const float* __restrict__ bias,
              const float* __restrict__ mask,
              float* __restrict__ out) {
    __shared__ float ws[PPV * WPAD];     //  8,448 B
    __shared__ float xw[NT * XWPAD];     //  5,120 B
    __shared__ float cbs[CO * PPV];      //  1,024 B
    __shared__ float ms[CO];             //     64 B  (total ~14.7 KB)

    const int t  = threadIdx.x;
    const int nt = blockIdx.x;           // 0..15
    const int b  = blockIdx.y;           // 0..31

    // ---- Phase 0 --------------------------------------------------------
    {
        const float4* wg4 = reinterpret_cast<const float4*>(W);
        #pragma unroll
        for (int k = 0; k < 2; k++) {
            int j = t + k * 256;         // 0..511
            int row = j >> 5, i = j & 31;
            *reinterpret_cast<float4*>(&ws[row * WPAD + i * 4]) = wg4[j];
        }
        if (t < CO) ms[t] = mask[b * CO + t];
    }
    __syncthreads();

    // ---- Phase 1: GEMV, 1 n-row x 4 p per thread ------------------------
    {
        const int row = t >> 2;          // 0..63 local n
        const int pg  = t & 3;           // p = pg + 4j
        const ulonglong2* xr = reinterpret_cast<const ulonglong2*>(
            x + ((size_t)b * (HG * HG) + (size_t)nt * NT + row) * DD);

        unsigned long long acc[4] = {0ull, 0ull, 0ull, 0ull};
        #pragma unroll 8
        for (int i = 0; i < 32; i++) {   // 16 B of x per iter
            ulonglong2 xa = __ldg(&xr[i]);
            #pragma unroll
            for (int j = 0; j < 4; j++) {
                ulonglong2 wv = *reinterpret_cast<const ulonglong2*>(
                    &ws[(pg + 4 * j) * WPAD + i * 4]);
                ffma2(acc[j], xa.x, wv.x);
                ffma2(acc[j], xa.y, wv.y);
            }
        }
        #pragma unroll
        for (int j = 0; j < 4; j++)
            xw[row * XWPAD + pg + 4 * j] = hsum2(acc[j]);
    }

    // ---- Phase 1b: cb[c][p] (one dot per thread; emb is L2-broadcast) ---
    {
        const int c = t >> 4;            // 0..15
        const int p = t & 15;            // 0..15
        const ulonglong2* eg = reinterpret_cast<const ulonglong2*>(emb + c * DD);
        unsigned long long acc = 0ull;
        #pragma unroll 8
        for (int i = 0; i < 32; i++) {
            ulonglong2 e = __ldg(&eg[i]);
            ulonglong2 wv = *reinterpret_cast<const ulonglong2*>(&ws[p * WPAD + i * 4]);
            ffma2(acc, e.x, wv.x);
            ffma2(acc, e.y, wv.y);
        }
        cbs[c * PPV + p] = hsum2(acc) + __ldg(&bias[p]);
    }
    __syncthreads();

    // ---- Phase 2: broadcast over channels, mask, store ------------------
    {
        const int r     = t >> 5;        // 0..7 : image row within block
        const int hl    = r >> 2;        // 0..1 : h-row within tile
        const int pr    = r & 3;         // patch row
        const int colf4 = t & 31;        // float4 along width == lane

        const int n_local = hl * 32 + colf4;
        const float4 y4 = *reinterpret_cast<const float4*>(
            &xw[n_local * XWPAD + pr * 4]);           // conflict-free (stride 20)

        const int grow = (nt * 2 + hl) * 4 + pr;      // global image row
        float* ob = out + (((size_t)b * CO) * 128 + grow) * 128 + colf4 * 4;

        #pragma unroll
        for (int cb4i = 0; cb4i < 4; cb4i++) {        // 4 channels per burst
            float4 o[4];
            #pragma unroll
            for (int u = 0; u < 4; u++) {
                int c = cb4i * 4 + u;
                float4 cb4 = *reinterpret_cast<const float4*>(&cbs[c * PPV + pr * 4]);
                float  m   = ms[c];
                o[u].x = (y4.x + cb4.x) * m;
                o[u].y = (y4.y + cb4.y) * m;
                o[u].z = (y4.z + cb4.z) * m;
                o[u].w = (y4.w + cb4.w) * m;
            }
            #pragma unroll
            for (int u = 0; u < 4; u++) {
                int c = cb4i * 4 + u;
                *reinterpret_cast<float4*>(ob + (size_t)c * (128 * 128)) = o[u];
            }
        }
    }
}

// ---------------------------------------------------------------------------
extern "C" void kernel_launch(void* const* d_in, const int* in_sizes, int n_in,
                              void* d_out, int out_size) {
    const float* x    = (const float*)d_in[0];   // (32, 1024, 128)
    const float* mask = (const float*)d_in[1];   // (32, 16)
    const float* emb  = (const float*)d_in[2];   // (256, 128)
    const float* W    = (const float*)d_in[3];   // (16, 128)
    const float* bias = (const float*)d_in[4];   // (16,)
    float* out = (float*)d_out;                  // (32, 16, 128, 128)

    dim3 grid(HG * HG / NT, NB);                 // (16, 32) = 512 blocks
    decoder_fused<<<grid, 256>>>(x, W, emb, bias, mask, out);
}